// round 16
// baseline (speedup 1.0000x reference)
#include <cuda_runtime.h>
#include <cuda_fp16.h>
#include <cstdint>

#define TSEQ 1024
#define EDIM 256
#define EH   2048
#define ROWS 8192
#define QSCALE 0.09016843980556021f   // log2(e)/16, folded into Q

// ---------------- scratch (fp16 operands, fp32 stats) ----------------
__device__ __align__(16) __half g_xr[ROWS * (size_t)EDIM];
__device__ __align__(16) __half g_q [ROWS * (size_t)EH];
__device__ __align__(16) __half g_k [ROWS * (size_t)EH];
__device__ __align__(16) __half g_vt[64 * (size_t)EDIM * TSEQ];  // [bh][n][j]
__device__ __align__(16) __half g_s [64LL * TSEQ * TSEQ];        // [bh][i][j] = exp(s/16)
__device__ __align__(16) float  g_rsum[64 * TSEQ];
__device__ __align__(16) __half g_o [ROWS * (size_t)EH];
__device__ __align__(16) __half g_wt[4 * (size_t)EH * EDIM];     // WqT,WkT,WvT,WuT (K-contig)

// ---------------- helpers ----------------
__device__ __forceinline__ uint32_t smem_u32(const void* p) {
    uint32_t a;
    asm("{ .reg .u64 t; cvta.to.shared.u64 t, %1; cvt.u32.u64 %0, t; }" : "=r"(a) : "l"(p));
    return a;
}
__device__ __forceinline__ float ex2f(float x) {
    float r; asm("ex2.approx.f32 %0, %1;" : "=f"(r) : "f"(x)); return r;
}
__device__ __forceinline__ void mma_f16(float* c, const uint32_t* a, const uint32_t* b) {
    asm volatile("mma.sync.aligned.m16n8k16.row.col.f32.f16.f16.f32 "
                 "{%0,%1,%2,%3}, {%4,%5,%6,%7}, {%8,%9}, {%0,%1,%2,%3};"
                 : "+f"(c[0]), "+f"(c[1]), "+f"(c[2]), "+f"(c[3])
                 : "r"(a[0]), "r"(a[1]), "r"(a[2]), "r"(a[3]), "r"(b[0]), "r"(b[1]));
}
#define LDSM_X4(r0, r1, r2, r3, addr) \
    asm volatile("ldmatrix.sync.aligned.m8n8.x4.shared.b16 {%0,%1,%2,%3}, [%4];" \
                 : "=r"(r0), "=r"(r1), "=r"(r2), "=r"(r3) : "r"(addr))
#define CP16(dst, src) \
    asm volatile("cp.async.cg.shared.global [%0], [%1], 16;" :: "r"(dst), "l"(src))
#define CP_COMMIT()  asm volatile("cp.async.commit_group;")
#define CP_WAIT1()   asm volatile("cp.async.wait_group 1;")
#define CP_WAIT0()   asm volatile("cp.async.wait_group 0;")

__device__ __forceinline__ uint32_t h2u(__half2 h) { return *(uint32_t*)&h; }

// BK=64 stage: 128 rows x 64 halves = 128 B/row, 8x16B chunks, 8-way XOR swizzle
#define STAGES    3
#define STAGE_B   32768
#define SMEM_BYTES (STAGES * STAGE_B)   // 96 KB; 2 CTAs/SM (192 <= 228 KB)

__device__ __forceinline__ void issue_stage(uint32_t sb, int s,
                                            const __half* __restrict__ A, int lda,
                                            const __half* __restrict__ B, int ldb,
                                            int k0, int tid)
{
    const uint32_t abase = sb + s * STAGE_B;
    const uint32_t bbase = abase + 16384;
    const int r0 = tid >> 3;
    const int c  = tid & 7;
    const __half* asrc = A + (size_t)r0 * lda + k0 + c * 8;
    const __half* bsrc = B + (size_t)r0 * ldb + k0 + c * 8;
    #pragma unroll
    for (int w = 0; w < 8; ++w) {
        const int row = w * 16 + r0;
        const uint32_t off = (uint32_t)(row * 128 + ((c ^ (row & 7)) << 4));
        CP16(abase + off, asrc + (size_t)w * 16 * lda);
        CP16(bbase + off, bsrc + (size_t)w * 16 * ldb);
    }
    CP_COMMIT();
}

__device__ __forceinline__ void compute_stage(uint32_t abase, uint32_t bbase,
                                              float acc[4][8][4], int wm, int wn, int lane)
{
    const int arow = wm * 64 + (lane & 15);
    const int achi = lane >> 4;
    const int brow = wn * 64 + (lane & 7) + ((lane >> 4) << 3);
    const int bchi = (lane >> 3) & 1;

    #pragma unroll
    for (int ks = 0; ks < 4; ++ks) {
        uint32_t bf[4][4];
        #pragma unroll
        for (int np = 0; np < 4; ++np) {
            const int r = brow + np * 16;
            const uint32_t ad = bbase + (uint32_t)(r * 128 + ((((ks << 1) + bchi) ^ (r & 7)) << 4));
            LDSM_X4(bf[np][0], bf[np][1], bf[np][2], bf[np][3], ad);
        }
        uint32_t af[4][4];
        #pragma unroll
        for (int mt = 0; mt < 4; ++mt) {
            const int r = arow + mt * 16;
            const uint32_t ad = abase + (uint32_t)(r * 128 + ((((ks << 1) + achi) ^ (r & 7)) << 4));
            LDSM_X4(af[mt][0], af[mt][1], af[mt][2], af[mt][3], ad);
        }
        #pragma unroll
        for (int mt = 0; mt < 4; ++mt)
            #pragma unroll
            for (int nt = 0; nt < 8; ++nt)
                mma_f16(acc[mt][nt], af[mt], &bf[nt >> 1][(nt & 1) * 2]);
    }
}

// D[128x128] = A[128xK] . B[128xK]^T  (halves, K multiple of 64; 3-buffer pipeline)
__device__ __forceinline__ void gemm_mma(const __half* __restrict__ A, int lda,
                                         const __half* __restrict__ B, int ldb,
                                         int K, float acc[4][8][4], uint32_t sb)
{
    const int tid = threadIdx.x;
    const int wid = tid >> 5, lane = tid & 31;
    const int wm = wid & 1, wn = wid >> 1;
    const int KC = K >> 6;

    issue_stage(sb, 0, A, lda, B, ldb, 0, tid);
    if (KC > 1) issue_stage(sb, 1, A, lda, B, ldb, 64, tid);

    int s = 0;
    for (int c = 0; c < KC; ++c) {
        if (c + 2 < KC) CP_WAIT1(); else CP_WAIT0();
        __syncthreads();   // stage-c data ready AND all warps done reading stage c-1
        if (c + 2 < KC) {
            int ns = s + 2; if (ns >= STAGES) ns -= STAGES;
            issue_stage(sb, ns, A, lda, B, ldb, (c + 2) * 64, tid);
        }
        const uint32_t ab = sb + s * STAGE_B;
        compute_stage(ab, ab + 16384, acc, wm, wn, lane);
        if (++s == STAGES) s = 0;
    }
    __syncthreads();       // protect smem reuse by epilogues
}

// epilogue storing __half; SCALE applied after bias (for Q folding)
__device__ __forceinline__ void epi_half(float acc[4][8][4], __half* C, int ldc,
                                         const float* bias, float scale)
{
    const int wid = threadIdx.x >> 5, lane = threadIdx.x & 31;
    const int wm = wid & 1, wn = wid >> 1;
    #pragma unroll
    for (int mt = 0; mt < 4; ++mt) {
        const int m = wm * 64 + mt * 16 + (lane >> 2);
        #pragma unroll
        for (int nt = 0; nt < 8; ++nt) {
            const int n = wn * 64 + nt * 8 + (lane & 3) * 2;
            float b0 = 0.f, b1 = 0.f;
            if (bias) { b0 = bias[n]; b1 = bias[n + 1]; }
            *(__half2*)(C + (size_t)m * ldc + n) =
                __floats2half2_rn((acc[mt][nt][0] + b0) * scale, (acc[mt][nt][1] + b1) * scale);
            *(__half2*)(C + (size_t)(m + 8) * ldc + n) =
                __floats2half2_rn((acc[mt][nt][2] + b0) * scale, (acc[mt][nt][3] + b1) * scale);
        }
    }
}

// ---------------- kernels ----------------

__global__ __launch_bounds__(256) void round_x(const float* __restrict__ x)
{
    const size_t i = ((size_t)blockIdx.x * 256 + threadIdx.x) * 4;
    float4 v = *(const float4*)(x + i);
    uint2 u = { h2u(__floats2half2_rn(v.x, v.y)), h2u(__floats2half2_rn(v.z, v.w)) };
    *(uint2*)(g_xr + i) = u;
}

__global__ __launch_bounds__(256) void transpose_w(const float* __restrict__ Wq,
                                                   const float* __restrict__ Wk,
                                                   const float* __restrict__ Wv,
                                                   const float* __restrict__ Wu)
{
    const int z = blockIdx.z;
    const float* src; __half* dst; int R, C;
    if (z < 3) { src = (z == 0) ? Wq : (z == 1) ? Wk : Wv; dst = g_wt + (size_t)z * 524288; R = EDIM; C = EH; }
    else       { src = Wu; dst = g_wt + 3 * 524288; R = EH; C = EDIM; }
    const int cb = blockIdx.x * 32, rb = blockIdx.y * 32;
    if (cb >= C || rb >= R) return;
    __shared__ float t[32][33];
    const int tx = threadIdx.x & 31, ty = threadIdx.x >> 5;
    #pragma unroll
    for (int i = ty; i < 32; i += 8)
        t[i][tx] = src[(size_t)(rb + i) * C + cb + tx];
    __syncthreads();
    #pragma unroll
    for (int i = ty; i < 32; i += 8)
        dst[(size_t)(cb + i) * R + rb + tx] = __float2half_rn(t[tx][i]);
}

// 1) QKV. z==0 -> g_q scaled by QSCALE; z==1 -> g_k; z==2 -> g_vt transposed.
__global__ __launch_bounds__(128) void qkv_gemm(const float* __restrict__ bq,
                                                const float* __restrict__ bk,
                                                const float* __restrict__ bv)
{
    extern __shared__ __align__(1024) unsigned char sbuf[];
    const uint32_t sb = smem_u32(sbuf);
    const int z = blockIdx.z, col0 = blockIdx.x * 128, row0 = blockIdx.y * 128;
    const __half* A = g_xr + (size_t)row0 * EDIM;
    const __half* B = g_wt + (size_t)z * 524288 + (size_t)col0 * EDIM;
    float acc[4][8][4] = {};
    gemm_mma(A, EDIM, B, EDIM, EDIM, acc, sb);

    if (z < 2) {
        __half* C = (z == 0 ? g_q : g_k) + (size_t)row0 * EH + col0;
        const float* bias = (z == 0 ? bq : bk) + col0;
        epi_half(acc, C, EH, bias, z == 0 ? QSCALE : 1.0f);
        return;
    }
    const int wid = threadIdx.x >> 5, lane = threadIdx.x & 31;
    const int wm = wid & 1, wn = wid >> 1;
    const int b = row0 >> 10, i0 = row0 & 1023;
    const int vrow0 = (b * 8 + (col0 >> 8)) * 256 + (col0 & 255);
    const float* bias = bv + col0;
    float* st = (float*)sbuf;                 // [64][132]
    #pragma unroll
    for (int hf = 0; hf < 2; ++hf) {
        __syncthreads();
        if (wn == hf) {
            #pragma unroll
            for (int mt = 0; mt < 4; ++mt) {
                const int m = wm * 64 + mt * 16 + (lane >> 2);
                #pragma unroll
                for (int nt = 0; nt < 8; ++nt) {
                    const int nl = nt * 8 + (lane & 3) * 2;
                    const float b0 = bias[hf * 64 + nl], b1 = bias[hf * 64 + nl + 1];
                    st[nl * 132 + m]             = acc[mt][nt][0] + b0;
                    st[(nl + 1) * 132 + m]       = acc[mt][nt][1] + b1;
                    st[nl * 132 + m + 8]         = acc[mt][nt][2] + b0;
                    st[(nl + 1) * 132 + m + 8]   = acc[mt][nt][3] + b1;
                }
            }
        }
        __syncthreads();
        #pragma unroll
        for (int r = 0; r < 16; ++r) {
            const int nl = wid * 16 + r;
            float4 v = *(float4*)(st + nl * 132 + lane * 4);
            uint2 u = { h2u(__floats2half2_rn(v.x, v.y)), h2u(__floats2half2_rn(v.z, v.w)) };
            *(uint2*)(g_vt + (size_t)(vrow0 + hf * 64 + nl) * TSEQ + i0 + lane * 4) = u;
        }
    }
}

// 2) scores: P = 2^(Q'.K^T) (= exp(QK/16)) as half, masked (clean epilogue, no atomics)
__global__ __launch_bounds__(128) void scores_gemm()
{
    const int jt = blockIdx.x, it = blockIdx.y, bh = blockIdx.z;
    if (jt > it) return;
    extern __shared__ __align__(1024) unsigned char sbuf[];
    const uint32_t sb = smem_u32(sbuf);
    const int b = bh >> 3, h = bh & 7;
    const __half* A = g_q + (size_t)(b * TSEQ + it * 128) * EH + h * EDIM;
    const __half* B = g_k + (size_t)(b * TSEQ + jt * 128) * EH + h * EDIM;
    float acc[4][8][4] = {};
    gemm_mma(A, EH, B, EH, EDIM, acc, sb);

    __half* C = g_s + ((size_t)bh << 20) + (size_t)(it * 128) * TSEQ + jt * 128;
    const int wid = threadIdx.x >> 5, lane = threadIdx.x & 31;
    const int wm = wid & 1, wn = wid >> 1;
    const bool full = (jt < it);
    #pragma unroll
    for (int mt = 0; mt < 4; ++mt) {
        const int m = wm * 64 + mt * 16 + (lane >> 2);
        #pragma unroll
        for (int nt = 0; nt < 8; ++nt) {
            const int n = wn * 64 + nt * 8 + (lane & 3) * 2;
            float e0 = ex2f(acc[mt][nt][0]);
            float e1 = ex2f(acc[mt][nt][1]);
            float e2 = ex2f(acc[mt][nt][2]);
            float e3 = ex2f(acc[mt][nt][3]);
            if (!full) {
                if (n >= m)         e0 = 0.f;
                if (n + 1 >= m)     e1 = 0.f;
                if (n >= m + 8)     e2 = 0.f;
                if (n + 1 >= m + 8) e3 = 0.f;
            }
            *(__half2*)(C + (size_t)m * TSEQ + n)       = __floats2half2_rn(e0, e1);
            *(__half2*)(C + (size_t)(m + 8) * TSEQ + n) = __floats2half2_rn(e2, e3);
        }
    }
}

// 3) rowsum over half P (sums EXACTLY the values GEMM2 consumes)
__global__ __launch_bounds__(256) void rowsum_kernel()
{
    const int wid = threadIdx.x >> 5, lane = threadIdx.x & 31;
    const int r = blockIdx.x * 8 + wid;
    const int i = r & (TSEQ - 1);
    const int klim = ((i >> 7) + 1) << 7;
    const __half* p = g_s + (size_t)r * TSEQ;
    float s = 0.f;
    for (int jb = lane * 8; jb < klim; jb += 256) {
        uint4 u = *(const uint4*)(p + jb);
        float2 f0 = __half22float2(*(__half2*)&u.x);
        float2 f1 = __half22float2(*(__half2*)&u.y);
        float2 f2 = __half22float2(*(__half2*)&u.z);
        float2 f3 = __half22float2(*(__half2*)&u.w);
        s += (f0.x + f0.y) + (f1.x + f1.y) + (f2.x + f2.y) + (f3.x + f3.y);
    }
    #pragma unroll
    for (int d = 16; d > 0; d >>= 1) s += __shfl_xor_sync(0xffffffffu, s, d);
    if (lane == 0) g_rsum[r] = s;
}

// 4) attnv: O = (P_unnorm @ Vt^T) * inv_rowsum; it descending for balance
__global__ __launch_bounds__(128) void attnv_gemm()
{
    const int nt0 = blockIdx.x, it = 7 - (int)blockIdx.y, bh = blockIdx.z;
    extern __shared__ __align__(1024) unsigned char sbuf[];
    const uint32_t sb = smem_u32(sbuf);
    const int b = bh >> 3, h = bh & 7;
    const __half* A = g_s + ((size_t)bh << 20) + (size_t)(it * 128) * TSEQ;
    const __half* B = g_vt + ((size_t)bh * EDIM + nt0 * 128) * TSEQ;
    float acc[4][8][4] = {};
    gemm_mma(A, TSEQ, B, TSEQ, (it + 1) * 128, acc, sb);

    __half* C = g_o + (size_t)(b * TSEQ + it * 128) * EH + h * EDIM + nt0 * 128;
    const float* rs = g_rsum + bh * TSEQ + it * 128;
    const int wid = threadIdx.x >> 5, lane = threadIdx.x & 31;
    const int wm = wid & 1, wn = wid >> 1;
    #pragma unroll
    for (int mt = 0; mt < 4; ++mt) {
        const int m = wm * 64 + mt * 16 + (lane >> 2);
        const float s0 = rs[m], s1 = rs[m + 8];
        const float i0 = (s0 > 0.f) ? __fdividef(1.f, s0) : 0.f;
        const float i1 = (s1 > 0.f) ? __fdividef(1.f, s1) : 0.f;
        #pragma unroll
        for (int nt = 0; nt < 8; ++nt) {
            const int n = wn * 64 + nt * 8 + (lane & 3) * 2;
            *(__half2*)(C + (size_t)m * EH + n) =
                __floats2half2_rn(acc[mt][nt][0] * i0, acc[mt][nt][1] * i0);
            *(__half2*)(C + (size_t)(m + 8) * EH + n) =
                __floats2half2_rn(acc[mt][nt][2] * i1, acc[mt][nt][3] * i1);
        }
    }
}

// 5) proj: split-K x2, atomicAdd into zeroed out; bias added by z==0
__global__ __launch_bounds__(128) void proj_gemm(const float* __restrict__ bu,
                                                 float* __restrict__ out)
{
    const int col0 = blockIdx.x * 128, row0 = blockIdx.y * 128, z = blockIdx.z;
    extern __shared__ __align__(1024) unsigned char sbuf[];
    const uint32_t sb = smem_u32(sbuf);
    const __half* A = g_o + (size_t)row0 * EH + z * 1024;
    const __half* B = g_wt + 3 * 524288 + (size_t)col0 * EH + z * 1024;
    float acc[4][8][4] = {};
    gemm_mma(A, EH, B, EH, 1024, acc, sb);

    float* C = out + (size_t)row0 * EDIM + col0;
    const float* bias = bu + col0;
    const int wid = threadIdx.x >> 5, lane = threadIdx.x & 31;
    const int wm = wid & 1, wn = wid >> 1;
    #pragma unroll
    for (int mt = 0; mt < 4; ++mt) {
        const int m = wm * 64 + mt * 16 + (lane >> 2);
        #pragma unroll
        for (int nt = 0; nt < 8; ++nt) {
            const int n = wn * 64 + nt * 8 + (lane & 3) * 2;
            float b0 = 0.f, b1 = 0.f;
            if (z == 0) { b0 = bias[n]; b1 = bias[n + 1]; }
            atomicAdd(C + (size_t)m * EDIM + n,           acc[mt][nt][0] + b0);
            atomicAdd(C + (size_t)m * EDIM + n + 1,       acc[mt][nt][1] + b1);
            atomicAdd(C + (size_t)(m + 8) * EDIM + n,     acc[mt][nt][2] + b0);
            atomicAdd(C + (size_t)(m + 8) * EDIM + n + 1, acc[mt][nt][3] + b1);
        }
    }
}

// ---------------------------------------------------------------------------
extern "C" void kernel_launch(void* const* d_in, const int* in_sizes, int n_in,
                              void* d_out, int out_size)
{
    (void)in_sizes; (void)n_in;
    const float* x  = (const float*)d_in[0];
    const float* Wq = (const float*)d_in[1];
    const float* bq = (const float*)d_in[2];
    const float* Wk = (const float*)d_in[3];
    const float* bk = (const float*)d_in[4];
    const float* Wv = (const float*)d_in[5];
    const float* bv = (const float*)d_in[6];
    const float* Wu = (const float*)d_in[7];
    const float* bu = (const float*)d_in[8];
    float* out = (float*)d_out;

    static bool attr_done = false;
    if (!attr_done) {
        cudaFuncSetAttribute(qkv_gemm,   cudaFuncAttributeMaxDynamicSharedMemorySize, SMEM_BYTES);
        cudaFuncSetAttribute(scores_gemm,cudaFuncAttributeMaxDynamicSharedMemorySize, SMEM_BYTES);
        cudaFuncSetAttribute(attnv_gemm, cudaFuncAttributeMaxDynamicSharedMemorySize, SMEM_BYTES);
        cudaFuncSetAttribute(proj_gemm,  cudaFuncAttributeMaxDynamicSharedMemorySize, SMEM_BYTES);
        attr_done = true;
    }

    cudaMemsetAsync(out, 0, (size_t)out_size * sizeof(float), 0);

    round_x       <<<dim3(ROWS * EDIM / 1024), 256>>>(x);
    transpose_w   <<<dim3(64, 64, 4), 256>>>(Wq, Wk, Wv, Wu);
    qkv_gemm      <<<dim3(16, 64, 3), 128, SMEM_BYTES>>>(bq, bk, bv);
    scores_gemm   <<<dim3(8, 8, 64), 128, SMEM_BYTES>>>();
    rowsum_kernel <<<dim3(64 * TSEQ / 8), 256>>>();
    attnv_gemm    <<<dim3(2, 8, 64), 128, SMEM_BYTES>>>();
    proj_gemm     <<<dim3(2, 64, 2), 128, SMEM_BYTES>>>(bu, out);
}

// round 17
// speedup vs baseline: 1.0439x; 1.0439x over previous
#include <cuda_runtime.h>
#include <cuda_fp16.h>
#include <cstdint>

#define TSEQ 1024
#define EDIM 256
#define EH   2048
#define ROWS 8192
#define QSCALE 0.09016843980556021f   // log2(e)/16, folded into Q

// ---------------- scratch (fp16 operands) ----------------
__device__ __align__(16) __half g_xr[ROWS * (size_t)EDIM];
__device__ __align__(16) __half g_q [ROWS * (size_t)EH];
__device__ __align__(16) __half g_k [ROWS * (size_t)EH];
__device__ __align__(16) __half g_vt[64 * (size_t)EDIM * TSEQ];  // [bh][n][j]
__device__ __align__(16) __half g_s [64LL * TSEQ * TSEQ];        // [bh][i][j] = exp(s/16)
__device__ __align__(16) __half g_o [ROWS * (size_t)EH];
__device__ __align__(16) __half g_wt[4 * (size_t)EH * EDIM];     // WqT,WkT,WvT,WuT (K-contig)

// ---------------- helpers ----------------
__device__ __forceinline__ uint32_t smem_u32(const void* p) {
    uint32_t a;
    asm("{ .reg .u64 t; cvta.to.shared.u64 t, %1; cvt.u32.u64 %0, t; }" : "=r"(a) : "l"(p));
    return a;
}
__device__ __forceinline__ float ex2f(float x) {
    float r; asm("ex2.approx.f32 %0, %1;" : "=f"(r) : "f"(x)); return r;
}
__device__ __forceinline__ void mma_f16(float* c, const uint32_t* a, const uint32_t* b) {
    asm volatile("mma.sync.aligned.m16n8k16.row.col.f32.f16.f16.f32 "
                 "{%0,%1,%2,%3}, {%4,%5,%6,%7}, {%8,%9}, {%0,%1,%2,%3};"
                 : "+f"(c[0]), "+f"(c[1]), "+f"(c[2]), "+f"(c[3])
                 : "r"(a[0]), "r"(a[1]), "r"(a[2]), "r"(a[3]), "r"(b[0]), "r"(b[1]));
}
#define LDSM_X4(r0, r1, r2, r3, addr) \
    asm volatile("ldmatrix.sync.aligned.m8n8.x4.shared.b16 {%0,%1,%2,%3}, [%4];" \
                 : "=r"(r0), "=r"(r1), "=r"(r2), "=r"(r3) : "r"(addr))
#define CP16(dst, src) \
    asm volatile("cp.async.cg.shared.global [%0], [%1], 16;" :: "r"(dst), "l"(src))
#define CP_COMMIT()  asm volatile("cp.async.commit_group;")
#define CP_WAIT1()   asm volatile("cp.async.wait_group 1;")
#define CP_WAIT0()   asm volatile("cp.async.wait_group 0;")

__device__ __forceinline__ uint32_t h2u(__half2 h) { return *(uint32_t*)&h; }

// BK=64 stage: 128 rows x 64 halves = 128 B/row, 8x16B chunks, 8-way XOR swizzle
#define STAGES    2
#define STAGE_B   32768
#define SMEM_BYTES (STAGES * STAGE_B)   // 64 KB -> 2 CTAs/SM

__device__ __forceinline__ void issue_stage(uint32_t sb, int s,
                                            const __half* __restrict__ A, int lda,
                                            const __half* __restrict__ B, int ldb,
                                            int k0, int tid)
{
    const uint32_t abase = sb + s * STAGE_B;
    const uint32_t bbase = abase + 16384;
    const int r0 = tid >> 3;
    const int c  = tid & 7;
    const __half* asrc = A + (size_t)r0 * lda + k0 + c * 8;
    const __half* bsrc = B + (size_t)r0 * ldb + k0 + c * 8;
    #pragma unroll
    for (int w = 0; w < 8; ++w) {
        const int row = w * 16 + r0;
        const uint32_t off = (uint32_t)(row * 128 + ((c ^ (row & 7)) << 4));
        CP16(abase + off, asrc + (size_t)w * 16 * lda);
        CP16(bbase + off, bsrc + (size_t)w * 16 * ldb);
    }
    CP_COMMIT();
}

// RSUM=0: plain; RSUM=1: wn==0 warps also accumulate fp32 row-sums of the A tile
template<int RSUM>
__device__ __forceinline__ void compute_stage_t(uint32_t abase, uint32_t bbase,
                                                float acc[4][8][4],
                                                float rs0[4], float rs1[4],
                                                int wm, int wn, int lane)
{
    const int arow = wm * 64 + (lane & 15);
    const int achi = lane >> 4;
    const int brow = wn * 64 + (lane & 7) + ((lane >> 4) << 3);
    const int bchi = (lane >> 3) & 1;

    #pragma unroll
    for (int ks = 0; ks < 4; ++ks) {
        uint32_t bf[4][4];
        #pragma unroll
        for (int np = 0; np < 4; ++np) {
            const int r = brow + np * 16;
            const uint32_t ad = bbase + (uint32_t)(r * 128 + ((((ks << 1) + bchi) ^ (r & 7)) << 4));
            LDSM_X4(bf[np][0], bf[np][1], bf[np][2], bf[np][3], ad);
        }
        uint32_t af[4][4];
        #pragma unroll
        for (int mt = 0; mt < 4; ++mt) {
            const int r = arow + mt * 16;
            const uint32_t ad = abase + (uint32_t)(r * 128 + ((((ks << 1) + achi) ^ (r & 7)) << 4));
            LDSM_X4(af[mt][0], af[mt][1], af[mt][2], af[mt][3], ad);
        }
        if (RSUM && wn == 0) {
            #pragma unroll
            for (int mt = 0; mt < 4; ++mt) {
                float2 f0 = __half22float2(*(__half2*)&af[mt][0]);  // row g
                float2 f1 = __half22float2(*(__half2*)&af[mt][1]);  // row g+8
                float2 f2 = __half22float2(*(__half2*)&af[mt][2]);  // row g
                float2 f3 = __half22float2(*(__half2*)&af[mt][3]);  // row g+8
                rs0[mt] += (f0.x + f0.y) + (f2.x + f2.y);
                rs1[mt] += (f1.x + f1.y) + (f3.x + f3.y);
            }
        }
        #pragma unroll
        for (int mt = 0; mt < 4; ++mt)
            #pragma unroll
            for (int nt = 0; nt < 8; ++nt)
                mma_f16(acc[mt][nt], af[mt], &bf[nt >> 1][(nt & 1) * 2]);
    }
}

// D[128x128] = A[128xK] . B[128xK]^T  (halves, K multiple of 64; double-buffered)
template<int RSUM>
__device__ __forceinline__ void gemm_mma_t(const __half* __restrict__ A, int lda,
                                           const __half* __restrict__ B, int ldb,
                                           int K, float acc[4][8][4],
                                           float rs0[4], float rs1[4], uint32_t sb)
{
    const int tid = threadIdx.x;
    const int wid = tid >> 5, lane = tid & 31;
    const int wm = wid & 1, wn = wid >> 1;
    const int KC = K >> 6;

    issue_stage(sb, 0, A, lda, B, ldb, 0, tid);
    int s = 0;
    for (int c = 0; c < KC; ++c) {
        if (c + 1 < KC) {
            __syncthreads();
            issue_stage(sb, s ^ 1, A, lda, B, ldb, (c + 1) * 64, tid);
            CP_WAIT1();
        } else {
            CP_WAIT0();
        }
        __syncthreads();
        const uint32_t ab = sb + s * STAGE_B;
        compute_stage_t<RSUM>(ab, ab + 16384, acc, rs0, rs1, wm, wn, lane);
        s ^= 1;
    }
    __syncthreads();
}

__device__ __forceinline__ void gemm_mma(const __half* __restrict__ A, int lda,
                                         const __half* __restrict__ B, int ldb,
                                         int K, float acc[4][8][4], uint32_t sb)
{
    float d0[4], d1[4];
    gemm_mma_t<0>(A, lda, B, ldb, K, acc, d0, d1, sb);
}

// epilogue storing __half; SCALE applied after bias (for Q folding)
__device__ __forceinline__ void epi_half(float acc[4][8][4], __half* C, int ldc,
                                         const float* bias, float scale)
{
    const int wid = threadIdx.x >> 5, lane = threadIdx.x & 31;
    const int wm = wid & 1, wn = wid >> 1;
    #pragma unroll
    for (int mt = 0; mt < 4; ++mt) {
        const int m = wm * 64 + mt * 16 + (lane >> 2);
        #pragma unroll
        for (int nt = 0; nt < 8; ++nt) {
            const int n = wn * 64 + nt * 8 + (lane & 3) * 2;
            float b0 = 0.f, b1 = 0.f;
            if (bias) { b0 = bias[n]; b1 = bias[n + 1]; }
            *(__half2*)(C + (size_t)m * ldc + n) =
                __floats2half2_rn((acc[mt][nt][0] + b0) * scale, (acc[mt][nt][1] + b1) * scale);
            *(__half2*)(C + (size_t)(m + 8) * ldc + n) =
                __floats2half2_rn((acc[mt][nt][2] + b0) * scale, (acc[mt][nt][3] + b1) * scale);
        }
    }
}

// ---------------- kernels ----------------

__global__ __launch_bounds__(256) void round_x(const float* __restrict__ x)
{
    const size_t i = ((size_t)blockIdx.x * 256 + threadIdx.x) * 4;
    float4 v = *(const float4*)(x + i);
    uint2 u = { h2u(__floats2half2_rn(v.x, v.y)), h2u(__floats2half2_rn(v.z, v.w)) };
    *(uint2*)(g_xr + i) = u;
}

__global__ __launch_bounds__(256) void transpose_w(const float* __restrict__ Wq,
                                                   const float* __restrict__ Wk,
                                                   const float* __restrict__ Wv,
                                                   const float* __restrict__ Wu)
{
    const int z = blockIdx.z;
    const float* src; __half* dst; int R, C;
    if (z < 3) { src = (z == 0) ? Wq : (z == 1) ? Wk : Wv; dst = g_wt + (size_t)z * 524288; R = EDIM; C = EH; }
    else       { src = Wu; dst = g_wt + 3 * 524288; R = EH; C = EDIM; }
    const int cb = blockIdx.x * 32, rb = blockIdx.y * 32;
    if (cb >= C || rb >= R) return;
    __shared__ float t[32][33];
    const int tx = threadIdx.x & 31, ty = threadIdx.x >> 5;
    #pragma unroll
    for (int i = ty; i < 32; i += 8)
        t[i][tx] = src[(size_t)(rb + i) * C + cb + tx];
    __syncthreads();
    #pragma unroll
    for (int i = ty; i < 32; i += 8)
        dst[(size_t)(cb + i) * R + rb + tx] = __float2half_rn(t[tx][i]);
}

// 1) QKV. z==0 -> g_q scaled by QSCALE; z==1 -> g_k; z==2 -> g_vt transposed.
__global__ __launch_bounds__(128) void qkv_gemm(const float* __restrict__ bq,
                                                const float* __restrict__ bk,
                                                const float* __restrict__ bv)
{
    extern __shared__ __align__(1024) unsigned char sbuf[];
    const uint32_t sb = smem_u32(sbuf);
    const int z = blockIdx.z, col0 = blockIdx.x * 128, row0 = blockIdx.y * 128;
    const __half* A = g_xr + (size_t)row0 * EDIM;
    const __half* B = g_wt + (size_t)z * 524288 + (size_t)col0 * EDIM;
    float acc[4][8][4] = {};
    gemm_mma(A, EDIM, B, EDIM, EDIM, acc, sb);

    if (z < 2) {
        __half* C = (z == 0 ? g_q : g_k) + (size_t)row0 * EH + col0;
        const float* bias = (z == 0 ? bq : bk) + col0;
        epi_half(acc, C, EH, bias, z == 0 ? QSCALE : 1.0f);
        return;
    }
    const int wid = threadIdx.x >> 5, lane = threadIdx.x & 31;
    const int wm = wid & 1, wn = wid >> 1;
    const int b = row0 >> 10, i0 = row0 & 1023;
    const int vrow0 = (b * 8 + (col0 >> 8)) * 256 + (col0 & 255);
    const float* bias = bv + col0;
    float* st = (float*)sbuf;                 // [64][132]
    #pragma unroll
    for (int hf = 0; hf < 2; ++hf) {
        __syncthreads();
        if (wn == hf) {
            #pragma unroll
            for (int mt = 0; mt < 4; ++mt) {
                const int m = wm * 64 + mt * 16 + (lane >> 2);
                #pragma unroll
                for (int nt = 0; nt < 8; ++nt) {
                    const int nl = nt * 8 + (lane & 3) * 2;
                    const float b0 = bias[hf * 64 + nl], b1 = bias[hf * 64 + nl + 1];
                    st[nl * 132 + m]             = acc[mt][nt][0] + b0;
                    st[(nl + 1) * 132 + m]       = acc[mt][nt][1] + b1;
                    st[nl * 132 + m + 8]         = acc[mt][nt][2] + b0;
                    st[(nl + 1) * 132 + m + 8]   = acc[mt][nt][3] + b1;
                }
            }
        }
        __syncthreads();
        #pragma unroll
        for (int r = 0; r < 16; ++r) {
            const int nl = wid * 16 + r;
            float4 v = *(float4*)(st + nl * 132 + lane * 4);
            uint2 u = { h2u(__floats2half2_rn(v.x, v.y)), h2u(__floats2half2_rn(v.z, v.w)) };
            *(uint2*)(g_vt + (size_t)(vrow0 + hf * 64 + nl) * TSEQ + i0 + lane * 4) = u;
        }
    }
}

// 2) scores: P = 2^(Q'.K^T) (= exp(QK/16)) as half, masked (clean epilogue)
__global__ __launch_bounds__(128) void scores_gemm()
{
    const int jt = blockIdx.x, it = blockIdx.y, bh = blockIdx.z;
    if (jt > it) return;
    extern __shared__ __align__(1024) unsigned char sbuf[];
    const uint32_t sb = smem_u32(sbuf);
    const int b = bh >> 3, h = bh & 7;
    const __half* A = g_q + (size_t)(b * TSEQ + it * 128) * EH + h * EDIM;
    const __half* B = g_k + (size_t)(b * TSEQ + jt * 128) * EH + h * EDIM;
    float acc[4][8][4] = {};
    gemm_mma(A, EH, B, EH, EDIM, acc, sb);

    __half* C = g_s + ((size_t)bh << 20) + (size_t)(it * 128) * TSEQ + jt * 128;
    const int wid = threadIdx.x >> 5, lane = threadIdx.x & 31;
    const int wm = wid & 1, wn = wid >> 1;
    const bool full = (jt < it);
    #pragma unroll
    for (int mt = 0; mt < 4; ++mt) {
        const int m = wm * 64 + mt * 16 + (lane >> 2);
        #pragma unroll
        for (int nt = 0; nt < 8; ++nt) {
            const int n = wn * 64 + nt * 8 + (lane & 3) * 2;
            float e0 = ex2f(acc[mt][nt][0]);
            float e1 = ex2f(acc[mt][nt][1]);
            float e2 = ex2f(acc[mt][nt][2]);
            float e3 = ex2f(acc[mt][nt][3]);
            if (!full) {
                if (n >= m)         e0 = 0.f;
                if (n + 1 >= m)     e1 = 0.f;
                if (n >= m + 8)     e2 = 0.f;
                if (n + 1 >= m + 8) e3 = 0.f;
            }
            *(__half2*)(C + (size_t)m * TSEQ + n)       = __floats2half2_rn(e0, e1);
            *(__half2*)(C + (size_t)(m + 8) * TSEQ + n) = __floats2half2_rn(e2, e3);
        }
    }
}

// 3) attnv with FUSED rowsum: O = (P @ Vt^T) * inv(rowsum(P)); rowsums from A-frags.
__global__ __launch_bounds__(128) void attnv_gemm()
{
    const int nt0 = blockIdx.x, it = 7 - (int)blockIdx.y, bh = blockIdx.z;
    extern __shared__ __align__(1024) unsigned char sbuf[];
    const uint32_t sb = smem_u32(sbuf);
    const int b = bh >> 3, h = bh & 7;
    const __half* A = g_s + ((size_t)bh << 20) + (size_t)(it * 128) * TSEQ;
    const __half* B = g_vt + ((size_t)bh * EDIM + nt0 * 128) * TSEQ;
    float acc[4][8][4] = {};
    float rs0[4] = {}, rs1[4] = {};
    gemm_mma_t<1>(A, TSEQ, B, TSEQ, (it + 1) * 128, acc, rs0, rs1, sb);

    const int wid = threadIdx.x >> 5, lane = threadIdx.x & 31;
    const int wm = wid & 1, wn = wid >> 1;
    float* srs = (float*)sbuf;                 // 128 floats (post-gemm smem reuse)

    if (wn == 0) {
        #pragma unroll
        for (int mt = 0; mt < 4; ++mt) {
            rs0[mt] += __shfl_xor_sync(0xffffffffu, rs0[mt], 1);
            rs0[mt] += __shfl_xor_sync(0xffffffffu, rs0[mt], 2);
            rs1[mt] += __shfl_xor_sync(0xffffffffu, rs1[mt], 1);
            rs1[mt] += __shfl_xor_sync(0xffffffffu, rs1[mt], 2);
            if ((lane & 3) == 0) {
                const int m = wm * 64 + mt * 16 + (lane >> 2);
                srs[m]     = rs0[mt];
                srs[m + 8] = rs1[mt];
            }
        }
    }
    __syncthreads();

    __half* C = g_o + (size_t)(b * TSEQ + it * 128) * EH + h * EDIM + nt0 * 128;
    #pragma unroll
    for (int mt = 0; mt < 4; ++mt) {
        const int m = wm * 64 + mt * 16 + (lane >> 2);
        const float s0 = srs[m], s1 = srs[m + 8];
        const float i0 = (s0 > 0.f) ? __fdividef(1.f, s0) : 0.f;
        const float i1 = (s1 > 0.f) ? __fdividef(1.f, s1) : 0.f;
        #pragma unroll
        for (int nt = 0; nt < 8; ++nt) {
            const int n = wn * 64 + nt * 8 + (lane & 3) * 2;
            *(__half2*)(C + (size_t)m * EH + n) =
                __floats2half2_rn(acc[mt][nt][0] * i0, acc[mt][nt][1] * i0);
            *(__half2*)(C + (size_t)(m + 8) * EH + n) =
                __floats2half2_rn(acc[mt][nt][2] * i1, acc[mt][nt][3] * i1);
        }
    }
}

// 4) proj: split-K x2, atomicAdd into zeroed out; bias added by z==0
__global__ __launch_bounds__(128) void proj_gemm(const float* __restrict__ bu,
                                                 float* __restrict__ out)
{
    const int col0 = blockIdx.x * 128, row0 = blockIdx.y * 128, z = blockIdx.z;
    extern __shared__ __align__(1024) unsigned char sbuf[];
    const uint32_t sb = smem_u32(sbuf);
    const __half* A = g_o + (size_t)row0 * EH + z * 1024;
    const __half* B = g_wt + 3 * 524288 + (size_t)col0 * EH + z * 1024;
    float acc[4][8][4] = {};
    gemm_mma(A, EH, B, EH, 1024, acc, sb);

    float* C = out + (size_t)row0 * EDIM + col0;
    const float* bias = bu + col0;
    const int wid = threadIdx.x >> 5, lane = threadIdx.x & 31;
    const int wm = wid & 1, wn = wid >> 1;
    #pragma unroll
    for (int mt = 0; mt < 4; ++mt) {
        const int m = wm * 64 + mt * 16 + (lane >> 2);
        #pragma unroll
        for (int nt = 0; nt < 8; ++nt) {
            const int n = wn * 64 + nt * 8 + (lane & 3) * 2;
            float b0 = 0.f, b1 = 0.f;
            if (z == 0) { b0 = bias[n]; b1 = bias[n + 1]; }
            atomicAdd(C + (size_t)m * EDIM + n,           acc[mt][nt][0] + b0);
            atomicAdd(C + (size_t)m * EDIM + n + 1,       acc[mt][nt][1] + b1);
            atomicAdd(C + (size_t)(m + 8) * EDIM + n,     acc[mt][nt][2] + b0);
            atomicAdd(C + (size_t)(m + 8) * EDIM + n + 1, acc[mt][nt][3] + b1);
        }
    }
}

// ---------------------------------------------------------------------------
extern "C" void kernel_launch(void* const* d_in, const int* in_sizes, int n_in,
                              void* d_out, int out_size)
{
    (void)in_sizes; (void)n_in;
    const float* x  = (const float*)d_in[0];
    const float* Wq = (const float*)d_in[1];
    const float* bq = (const float*)d_in[2];
    const float* Wk = (const float*)d_in[3];
    const float* bk = (const float*)d_in[4];
    const float* Wv = (const float*)d_in[5];
    const float* bv = (const float*)d_in[6];
    const float* Wu = (const float*)d_in[7];
    const float* bu = (const float*)d_in[8];
    float* out = (float*)d_out;

    static bool attr_done = false;
    if (!attr_done) {
        cudaFuncSetAttribute(qkv_gemm,   cudaFuncAttributeMaxDynamicSharedMemorySize, SMEM_BYTES);
        cudaFuncSetAttribute(scores_gemm,cudaFuncAttributeMaxDynamicSharedMemorySize, SMEM_BYTES);
        cudaFuncSetAttribute(attnv_gemm, cudaFuncAttributeMaxDynamicSharedMemorySize, SMEM_BYTES);
        cudaFuncSetAttribute(proj_gemm,  cudaFuncAttributeMaxDynamicSharedMemorySize, SMEM_BYTES);
        attr_done = true;
    }

    cudaMemsetAsync(out, 0, (size_t)out_size * sizeof(float), 0);

    round_x    <<<dim3(ROWS * EDIM / 1024), 256>>>(x);
    transpose_w<<<dim3(64, 64, 4), 256>>>(Wq, Wk, Wv, Wu);
    qkv_gemm   <<<dim3(16, 64, 3), 128, SMEM_BYTES>>>(bq, bk, bv);
    scores_gemm<<<dim3(8, 8, 64), 128, SMEM_BYTES>>>();
    attnv_gemm <<<dim3(2, 8, 64), 128, SMEM_BYTES>>>();
    proj_gemm  <<<dim3(2, 64, 2), 128, SMEM_BYTES>>>(bu, out);
}